// round 9
// baseline (speedup 1.0000x reference)
#include <cuda_runtime.h>
#include <cuda_bf16.h>
#include <cstdint>

#define NN 50000
#define NE 600000
#define DD 128
#define NC 64
#define SWIDE 136   // padded A-tile row stride (272B) -> conflict-free ldmatrix

// ---------------- scratch (no allocations allowed) ----------------
__device__ float g_xw[NN * DD];
__device__ int   g_deg[NN];
__device__ float g_dinv[NN];
__device__ int   g_cluster_edges[NC];
__device__ int   g_intra_src[NE];
__device__ int   g_intra_dst[NE];
__device__ int   g_intra_count;
__device__ int   g_is_src[NN];
// W^T hi/lo, compact row-major [n][k] (stride 128) — read via LDG (L1-resident)
__device__ __align__(16) __nv_bfloat16 g_wthi[DD * DD];
__device__ __align__(16) __nv_bfloat16 g_wtlo[DD * DD];

__device__ __forceinline__ void split_bf16(float v, __nv_bfloat16& h, __nv_bfloat16& l) {
    h = __float2bfloat16(v);
    l = __float2bfloat16(v - __bfloat162float(h));
}
__device__ __forceinline__ uint32_t pack2(__nv_bfloat16 a, __nv_bfloat16 b) {
    __nv_bfloat162 t; t.x = a; t.y = b;
    return *reinterpret_cast<uint32_t*>(&t);
}
__device__ __forceinline__ void mma16816(float c[4], const uint32_t a[4],
                                         uint32_t b0, uint32_t b1) {
    asm volatile(
        "mma.sync.aligned.m16n8k16.row.col.f32.bf16.bf16.f32 "
        "{%0,%1,%2,%3}, {%4,%5,%6,%7}, {%8,%9}, {%0,%1,%2,%3};"
        : "+f"(c[0]), "+f"(c[1]), "+f"(c[2]), "+f"(c[3])
        : "r"(a[0]), "r"(a[1]), "r"(a[2]), "r"(a[3]), "r"(b0), "r"(b1));
}
__device__ __forceinline__ void ldsm_x4(uint32_t r[4], uint32_t saddr) {
    asm volatile(
        "ldmatrix.sync.aligned.m8n8.x4.shared.b16 {%0,%1,%2,%3}, [%4];"
        : "=r"(r[0]), "=r"(r[1]), "=r"(r[2]), "=r"(r[3]) : "r"(saddr));
}
__device__ __forceinline__ uint32_t smem_to_u32(const void* p) {
    uint32_t a;
    asm("{ .reg .u64 t; cvta.to.shared.u64 t, %1; cvt.u32.u64 %0, t; }"
        : "=r"(a) : "l"(p));
    return a;
}

// ---------------- kernel 1: zero counters ----------------
__global__ void zero_kernel() {
    int i = blockIdx.x * blockDim.x + threadIdx.x;
    if (i < NN) { g_deg[i] = 0; g_is_src[i] = 0; }
    if (i < NC) g_cluster_edges[i] = 0;
    if (i == 0) g_intra_count = 0;
}

// ---------------- kernel 2: W^T bf16 hi/lo, compact row-major ----------------
__global__ void wprep_kernel(const float* __restrict__ W) {
    int i = blockIdx.x * blockDim.x + threadIdx.x;
    if (i >= DD * DD) return;
    int nrow = i >> 7;
    int k = i & 127;
    float v = W[k * DD + nrow];
    __nv_bfloat16 h, l;
    split_bf16(v, h, l);
    g_wthi[nrow * DD + k] = h;
    g_wtlo[nrow * DD + k] = l;
}

// ---------------- kernel 3: edge pass (mask + degree + warp-agg compact) ----
__global__ void edge_pass_kernel(const int* __restrict__ ei,
                                 const int* __restrict__ cl,
                                 int E) {
    int e = blockIdx.x * blockDim.x + threadIdx.x;
    int s = 0, d = 0, cs = 0;
    bool intra = false;
    if (e < E) {
        s = ei[e];
        d = ei[E + e];
        cs = cl[s];
        intra = (cs == cl[d]);
    }
    unsigned mask = __ballot_sync(0xFFFFFFFFu, intra);
    if (intra) {
        atomicAdd(&g_deg[d], 1);
        atomicAdd(&g_cluster_edges[cs], 1);
        g_is_src[s] = 1;
        int lane = threadIdx.x & 31;
        int leader = __ffs(mask) - 1;
        int base = 0;
        if (lane == leader) base = atomicAdd(&g_intra_count, __popc(mask));
        base = __shfl_sync(mask, base, leader);
        int pos = base + __popc(mask & ((1u << lane) - 1u));
        g_intra_src[pos] = s;
        g_intra_dst[pos] = d;
    }
}

// ---------------- kernel 4: fused HMMA GEMM + node epilogue ----------------
// 256 threads (8 warps), CTA tile M=64 x N=128, 2 CTAs/SM (phase overlap).
// Warp grid: 2 (M) x 4 (N); warp tile 32x32. A hi/lo in smem; W via LDG (L1).
#define ATILE (64 * SWIDE * 2)          // 17408 B
#define SM_B    0
#define SM_AHI  512
#define SM_ALO  (512 + ATILE)
#define SM_TOT  (512 + 2 * ATILE)

__global__ void __launch_bounds__(256, 2)
gemm_fused_kernel(const float* __restrict__ X,
                  const float* __restrict__ b,
                  const int* __restrict__ cl,
                  float* __restrict__ out,
                  int n) {
    extern __shared__ char smem[];
    float* bias = (float*)(smem + SM_B);
    __nv_bfloat16* Ahi = (__nv_bfloat16*)(smem + SM_AHI);
    __nv_bfloat16* Alo = (__nv_bfloat16*)(smem + SM_ALO);

    const int tid  = threadIdx.x;
    const int row0 = blockIdx.x * 64;

    if (tid < 128) bias[tid] = b[tid];

    // load X tile (64 rows), split, store padded
    {
        const float4* X4 = (const float4*)X;
        #pragma unroll
        for (int i = tid; i < 64 * 16; i += 256) {
            int row = i >> 4;
            int c   = i & 15;
            int grow = row0 + row;
            float4 a = make_float4(0.f, 0.f, 0.f, 0.f), a2 = a;
            if (grow < n) {
                a  = X4[grow * 32 + c * 2];
                a2 = X4[grow * 32 + c * 2 + 1];
            }
            float v[8] = {a.x, a.y, a.z, a.w, a2.x, a2.y, a2.z, a2.w};
            uint32_t hi[4], lo[4];
            #pragma unroll
            for (int j = 0; j < 4; j++) {
                __nv_bfloat16 h0, l0, h1, l1;
                split_bf16(v[2 * j], h0, l0);
                split_bf16(v[2 * j + 1], h1, l1);
                hi[j] = pack2(h0, h1);
                lo[j] = pack2(l0, l1);
            }
            *(uint4*)(Ahi + row * SWIDE + c * 8) = make_uint4(hi[0], hi[1], hi[2], hi[3]);
            *(uint4*)(Alo + row * SWIDE + c * 8) = make_uint4(lo[0], lo[1], lo[2], lo[3]);
        }
    }
    __syncthreads();

    const int wid  = tid >> 5;
    const int lane = tid & 31;
    const int mw   = wid >> 2;    // 0..1 -> M offset mw*32
    const int nwp  = wid & 3;     // 0..3 -> N offset nwp*32
    const int g    = lane >> 2;   // 0..7
    const int tg   = lane & 3;    // 0..3

    const uint32_t sbase = smem_to_u32(smem);
    const uint32_t aoff =
        ((uint32_t)(mw * 32 + (lane & 15)) * SWIDE + (uint32_t)(lane >> 4) * 8) * 2;
    const uint32_t AhiB = sbase + SM_AHI + aoff;
    const uint32_t AloB = sbase + SM_ALO + aoff;
    const uint32_t STEP16 = 16u * SWIDE * 2u;

    // B fragment u32 base indices: for nt, n = nwp*32 + nt*8 + g, k = ks*16 + tg*2
    const uint32_t* Whi32 = (const uint32_t*)g_wthi;
    const uint32_t* Wlo32 = (const uint32_t*)g_wtlo;
    const int bidx0 = ((nwp * 32 + g) * DD + tg * 2) >> 1;   // u32 units

    float acc[2][4][4];
    #pragma unroll
    for (int mt = 0; mt < 2; mt++)
        #pragma unroll
        for (int nt = 0; nt < 4; nt++)
            #pragma unroll
            for (int j = 0; j < 4; j++) acc[mt][nt][j] = 0.f;

    // pass 1: (Ahi + Alo) x Whi
    #pragma unroll
    for (int ks = 0; ks < 8; ks++) {
        const uint32_t ko = (uint32_t)ks * 32u;
        uint32_t ah0[4], ah1[4], al0[4], al1[4];
        ldsm_x4(ah0, AhiB + ko);
        ldsm_x4(ah1, AhiB + ko + STEP16);
        ldsm_x4(al0, AloB + ko);
        ldsm_x4(al1, AloB + ko + STEP16);
        #pragma unroll
        for (int nt = 0; nt < 4; nt++) {
            int bi = bidx0 + (nt * 8 * DD + ks * 16) / 2;
            uint32_t b0 = __ldg(Whi32 + bi);
            uint32_t b1 = __ldg(Whi32 + bi + 4);
            mma16816(acc[0][nt], ah0, b0, b1);
            mma16816(acc[1][nt], ah1, b0, b1);
            mma16816(acc[0][nt], al0, b0, b1);
            mma16816(acc[1][nt], al1, b0, b1);
        }
    }
    // pass 2: Ahi x Wlo
    #pragma unroll
    for (int ks = 0; ks < 8; ks++) {
        const uint32_t ko = (uint32_t)ks * 32u;
        uint32_t ah0[4], ah1[4];
        ldsm_x4(ah0, AhiB + ko);
        ldsm_x4(ah1, AhiB + ko + STEP16);
        #pragma unroll
        for (int nt = 0; nt < 4; nt++) {
            int bi = bidx0 + (nt * 8 * DD + ks * 16) / 2;
            uint32_t b0 = __ldg(Wlo32 + bi);
            uint32_t b1 = __ldg(Wlo32 + bi + 4);
            mma16816(acc[0][nt], ah0, b0, b1);
            mma16816(acc[1][nt], ah1, b0, b1);
        }
    }

    // dinv for this CTA's rows
    if (tid < 64) {
        int row = row0 + tid;
        if (row < n) g_dinv[row] = rsqrtf((float)g_deg[row] + 1.0f);
    }

    // fused node epilogue
    #pragma unroll
    for (int mt = 0; mt < 2; mt++) {
        #pragma unroll
        for (int half = 0; half < 2; half++) {
            int row = row0 + mw * 32 + mt * 16 + g + half * 8;
            if (row >= n) continue;
            float deg = (float)g_deg[row] + 1.0f;
            float inv = 1.0f / deg;
            bool  has = (g_cluster_edges[cl[row]] > 0);
            bool  src = (g_is_src[row] != 0);
            #pragma unroll
            for (int nt = 0; nt < 4; nt++) {
                int ncol = nwp * 32 + nt * 8 + tg * 2;
                float2 v = make_float2(acc[mt][nt][half * 2],
                                       acc[mt][nt][half * 2 + 1]);
                if (src) *(float2*)(g_xw + row * DD + ncol) = v;
                float2 o;
                if (has) {
                    o.x = fmaf(v.x, inv, bias[ncol]);
                    o.y = fmaf(v.y, inv, bias[ncol + 1]);
                } else {
                    o = *(const float2*)(X + row * DD + ncol);
                }
                *(float2*)(out + row * DD + ncol) = o;
            }
        }
    }
}

// ---------------- kernel 5: scatter over compacted intra edges --------------
__global__ void scatter_kernel(float* __restrict__ out) {
    int cnt  = g_intra_count;
    int gtid = blockIdx.x * blockDim.x + threadIdx.x;
    int warp = gtid >> 5;
    int lane = gtid & 31;
    int nw   = (gridDim.x * blockDim.x) >> 5;

    for (int e = warp; e < cnt; e += nw) {
        int s = g_intra_src[e];
        int d = g_intra_dst[e];
        float w = g_dinv[s] * g_dinv[d];
        float4 v = ((const float4*)(g_xw + s * DD))[lane];
        float* o = out + d * DD + lane * 4;
        atomicAdd(o + 0, w * v.x);
        atomicAdd(o + 1, w * v.y);
        atomicAdd(o + 2, w * v.z);
        atomicAdd(o + 3, w * v.w);
    }
}

// ---------------- launch ----------------
extern "C" void kernel_launch(void* const* d_in, const int* in_sizes, int n_in,
                              void* d_out, int out_size) {
    const float* X  = (const float*)d_in[0];
    const float* W  = (const float*)d_in[1];
    const float* b  = (const float*)d_in[2];
    // d_in[3] = edge_attr (unused)
    const int* cl = (const int*)d_in[4];
    const int* ei = (const int*)d_in[5];
    float* out = (float*)d_out;

    const int N = in_sizes[4];
    const int E = in_sizes[3];

    cudaFuncSetAttribute(gemm_fused_kernel,
                         cudaFuncAttributeMaxDynamicSharedMemorySize, SM_TOT);

    zero_kernel<<<(NN + 255) / 256, 256>>>();
    wprep_kernel<<<(DD * DD + 255) / 256, 256>>>(W);
    edge_pass_kernel<<<(E + 255) / 256, 256>>>(ei, cl, E);
    gemm_fused_kernel<<<(N + 63) / 64, 256, SM_TOT>>>(X, b, cl, out, N);
    scatter_kernel<<<512, 256>>>(out);
}

// round 12
// speedup vs baseline: 1.2588x; 1.2588x over previous
#include <cuda_runtime.h>
#include <cuda_bf16.h>
#include <cstdint>

#define NN 50000
#define NE 600000
#define DD 128
#define NC 64
#define SWIDE 136   // padded row stride in bf16 elems (272B) -> conflict-free ldmatrix

// ---------------- scratch (no allocations allowed) ----------------
__device__ float g_xw[NN * DD];
__device__ int   g_deg[NN];
__device__ float g_dinv[NN];
__device__ int   g_cluster_edges[NC];
__device__ int   g_intra_src[NE];
__device__ int   g_intra_dst[NE];
__device__ int   g_intra_count;
__device__ int   g_is_src[NN];
// W^T hi/lo, padded row-major [n][k] (row stride SWIDE) — copied to smem per CTA
__device__ __align__(16) __nv_bfloat16 g_wthi[DD * SWIDE];
__device__ __align__(16) __nv_bfloat16 g_wtlo[DD * SWIDE];

__device__ __forceinline__ void split_bf16(float v, __nv_bfloat16& h, __nv_bfloat16& l) {
    h = __float2bfloat16(v);
    l = __float2bfloat16(v - __bfloat162float(h));
}
__device__ __forceinline__ uint32_t pack2(__nv_bfloat16 a, __nv_bfloat16 b) {
    __nv_bfloat162 t; t.x = a; t.y = b;
    return *reinterpret_cast<uint32_t*>(&t);
}
__device__ __forceinline__ void mma16816(float c[4], const uint32_t a[4],
                                         uint32_t b0, uint32_t b1) {
    asm volatile(
        "mma.sync.aligned.m16n8k16.row.col.f32.bf16.bf16.f32 "
        "{%0,%1,%2,%3}, {%4,%5,%6,%7}, {%8,%9}, {%0,%1,%2,%3};"
        : "+f"(c[0]), "+f"(c[1]), "+f"(c[2]), "+f"(c[3])
        : "r"(a[0]), "r"(a[1]), "r"(a[2]), "r"(a[3]), "r"(b0), "r"(b1));
}
__device__ __forceinline__ void ldsm_x4(uint32_t r[4], uint32_t saddr) {
    asm volatile(
        "ldmatrix.sync.aligned.m8n8.x4.shared.b16 {%0,%1,%2,%3}, [%4];"
        : "=r"(r[0]), "=r"(r[1]), "=r"(r[2]), "=r"(r[3]) : "r"(saddr));
}
__device__ __forceinline__ uint32_t smem_to_u32(const void* p) {
    uint32_t a;
    asm("{ .reg .u64 t; cvta.to.shared.u64 t, %1; cvt.u32.u64 %0, t; }"
        : "=r"(a) : "l"(p));
    return a;
}

// ---------------- kernel 1: zero counters ----------------
__global__ void zero_kernel() {
    int i = blockIdx.x * blockDim.x + threadIdx.x;
    if (i < NN) { g_deg[i] = 0; g_is_src[i] = 0; }
    if (i < NC) g_cluster_edges[i] = 0;
    if (i == 0) g_intra_count = 0;
}

// ---------------- kernel 2: W^T bf16 hi/lo, padded row-major ----------------
__global__ void wprep_kernel(const float* __restrict__ W) {
    int i = blockIdx.x * blockDim.x + threadIdx.x;
    if (i >= DD * DD) return;
    int nrow = i >> 7;
    int k = i & 127;
    float v = W[k * DD + nrow];
    __nv_bfloat16 h, l;
    split_bf16(v, h, l);
    g_wthi[nrow * SWIDE + k] = h;
    g_wtlo[nrow * SWIDE + k] = l;
}

// ---------------- kernel 3: edge pass (mask + degree + warp-agg compact) ----
__global__ void edge_pass_kernel(const int* __restrict__ ei,
                                 const int* __restrict__ cl,
                                 int E) {
    int e = blockIdx.x * blockDim.x + threadIdx.x;
    int s = 0, d = 0, cs = 0;
    bool intra = false;
    if (e < E) {
        s = ei[e];
        d = ei[E + e];
        cs = cl[s];
        intra = (cs == cl[d]);
    }
    unsigned mask = __ballot_sync(0xFFFFFFFFu, intra);
    if (intra) {
        atomicAdd(&g_deg[d], 1);
        atomicAdd(&g_cluster_edges[cs], 1);
        g_is_src[s] = 1;
        int lane = threadIdx.x & 31;
        int leader = __ffs(mask) - 1;
        int base = 0;
        if (lane == leader) base = atomicAdd(&g_intra_count, __popc(mask));
        base = __shfl_sync(mask, base, leader);
        int pos = base + __popc(mask & ((1u << lane) - 1u));
        g_intra_src[pos] = s;
        g_intra_dst[pos] = d;
    }
}

// ---------------- kernel 4: fused HMMA GEMM + node epilogue ----------------
// 256 threads (8 warps), CTA tile M=64 x N=128, 2 independent CTAs per SM.
// Warp grid: 2 (M) x 4 (N); warp tile 32x32. A hi/lo + W hi/lo all in smem,
// all fragments via ldmatrix (conflict-free with SWIDE padding).
#define ATILE (64 * SWIDE * 2)          // 17408 B
#define WTILE (DD * SWIDE * 2)          // 34816 B
#define SM_B    0
#define SM_AHI  512
#define SM_ALO  (512 + ATILE)
#define SM_WHI  (512 + 2 * ATILE)
#define SM_WLO  (512 + 2 * ATILE + WTILE)
#define SM_TOT  (512 + 2 * ATILE + 2 * WTILE)   // 104960 B -> 2 CTAs/SM

__global__ void __launch_bounds__(256, 2)
gemm_fused_kernel(const float* __restrict__ X,
                  const float* __restrict__ b,
                  const int* __restrict__ cl,
                  float* __restrict__ out,
                  int n) {
    extern __shared__ char smem[];
    float* bias = (float*)(smem + SM_B);
    __nv_bfloat16* Ahi = (__nv_bfloat16*)(smem + SM_AHI);
    __nv_bfloat16* Alo = (__nv_bfloat16*)(smem + SM_ALO);

    const int tid  = threadIdx.x;
    const int row0 = blockIdx.x * 64;

    if (tid < 128) bias[tid] = b[tid];

    // copy padded W^T hi/lo images (34816B each = 2176 uint4)
    {
        const uint4* gh = (const uint4*)g_wthi;
        const uint4* gl = (const uint4*)g_wtlo;
        uint4* sh = (uint4*)(smem + SM_WHI);
        uint4* sl = (uint4*)(smem + SM_WLO);
        #pragma unroll
        for (int i = tid; i < 2176; i += 256) { sh[i] = gh[i]; sl[i] = gl[i]; }
    }

    // load X tile (64 rows), split, store padded
    {
        const float4* X4 = (const float4*)X;
        #pragma unroll
        for (int i = tid; i < 64 * 16; i += 256) {
            int row = i >> 4;
            int c   = i & 15;
            int grow = row0 + row;
            float4 a = make_float4(0.f, 0.f, 0.f, 0.f), a2 = a;
            if (grow < n) {
                a  = X4[grow * 32 + c * 2];
                a2 = X4[grow * 32 + c * 2 + 1];
            }
            float v[8] = {a.x, a.y, a.z, a.w, a2.x, a2.y, a2.z, a2.w};
            uint32_t hi[4], lo[4];
            #pragma unroll
            for (int j = 0; j < 4; j++) {
                __nv_bfloat16 h0, l0, h1, l1;
                split_bf16(v[2 * j], h0, l0);
                split_bf16(v[2 * j + 1], h1, l1);
                hi[j] = pack2(h0, h1);
                lo[j] = pack2(l0, l1);
            }
            *(uint4*)(Ahi + row * SWIDE + c * 8) = make_uint4(hi[0], hi[1], hi[2], hi[3]);
            *(uint4*)(Alo + row * SWIDE + c * 8) = make_uint4(lo[0], lo[1], lo[2], lo[3]);
        }
    }
    __syncthreads();

    const int wid  = tid >> 5;
    const int lane = tid & 31;
    const int mw   = wid >> 2;    // 0..1 -> M offset mw*32
    const int nwp  = wid & 3;     // 0..3 -> N offset nwp*32
    const int g    = lane >> 2;   // 0..7
    const int tg   = lane & 3;    // 0..3

    const uint32_t sbase = smem_to_u32(smem);
    const uint32_t aoff =
        ((uint32_t)(mw * 32 + (lane & 15)) * SWIDE + (uint32_t)(lane >> 4) * 8) * 2;
    const uint32_t boff =
        ((uint32_t)(nwp * 32 + ((lane >> 4) & 1) * 8 + (lane & 7)) * SWIDE
         + (uint32_t)((lane >> 3) & 1) * 8) * 2;
    const uint32_t AhiB = sbase + SM_AHI + aoff;
    const uint32_t AloB = sbase + SM_ALO + aoff;
    const uint32_t WhiB = sbase + SM_WHI + boff;
    const uint32_t WloB = sbase + SM_WLO + boff;
    const uint32_t STEP16 = 16u * SWIDE * 2u;

    float acc[2][4][4];
    #pragma unroll
    for (int mt = 0; mt < 2; mt++)
        #pragma unroll
        for (int nt = 0; nt < 4; nt++)
            #pragma unroll
            for (int j = 0; j < 4; j++) acc[mt][nt][j] = 0.f;

    // pass 1: (Ahi + Alo) x Whi  — B fragments loaded once, used 4x
    #pragma unroll
    for (int ks = 0; ks < 8; ks++) {
        const uint32_t ko = (uint32_t)ks * 32u;
        uint32_t ah0[4], ah1[4], al0[4], al1[4], b01[4], b23[4];
        ldsm_x4(b01, WhiB + ko);
        ldsm_x4(b23, WhiB + ko + STEP16);
        ldsm_x4(ah0, AhiB + ko);
        ldsm_x4(ah1, AhiB + ko + STEP16);
        ldsm_x4(al0, AloB + ko);
        ldsm_x4(al1, AloB + ko + STEP16);
        mma16816(acc[0][0], ah0, b01[0], b01[1]);
        mma16816(acc[0][1], ah0, b01[2], b01[3]);
        mma16816(acc[0][2], ah0, b23[0], b23[1]);
        mma16816(acc[0][3], ah0, b23[2], b23[3]);
        mma16816(acc[1][0], ah1, b01[0], b01[1]);
        mma16816(acc[1][1], ah1, b01[2], b01[3]);
        mma16816(acc[1][2], ah1, b23[0], b23[1]);
        mma16816(acc[1][3], ah1, b23[2], b23[3]);
        mma16816(acc[0][0], al0, b01[0], b01[1]);
        mma16816(acc[0][1], al0, b01[2], b01[3]);
        mma16816(acc[0][2], al0, b23[0], b23[1]);
        mma16816(acc[0][3], al0, b23[2], b23[3]);
        mma16816(acc[1][0], al1, b01[0], b01[1]);
        mma16816(acc[1][1], al1, b01[2], b01[3]);
        mma16816(acc[1][2], al1, b23[0], b23[1]);
        mma16816(acc[1][3], al1, b23[2], b23[3]);
    }
    // pass 2: Ahi x Wlo
    #pragma unroll
    for (int ks = 0; ks < 8; ks++) {
        const uint32_t ko = (uint32_t)ks * 32u;
        uint32_t ah0[4], ah1[4], b01[4], b23[4];
        ldsm_x4(b01, WloB + ko);
        ldsm_x4(b23, WloB + ko + STEP16);
        ldsm_x4(ah0, AhiB + ko);
        ldsm_x4(ah1, AhiB + ko + STEP16);
        mma16816(acc[0][0], ah0, b01[0], b01[1]);
        mma16816(acc[0][1], ah0, b01[2], b01[3]);
        mma16816(acc[0][2], ah0, b23[0], b23[1]);
        mma16816(acc[0][3], ah0, b23[2], b23[3]);
        mma16816(acc[1][0], ah1, b01[0], b01[1]);
        mma16816(acc[1][1], ah1, b01[2], b01[3]);
        mma16816(acc[1][2], ah1, b23[0], b23[1]);
        mma16816(acc[1][3], ah1, b23[2], b23[3]);
    }

    // dinv for this CTA's rows
    if (tid < 64) {
        int row = row0 + tid;
        if (row < n) g_dinv[row] = rsqrtf((float)g_deg[row] + 1.0f);
    }

    // fused node epilogue
    #pragma unroll
    for (int mt = 0; mt < 2; mt++) {
        #pragma unroll
        for (int half = 0; half < 2; half++) {
            int row = row0 + mw * 32 + mt * 16 + g + half * 8;
            if (row >= n) continue;
            float deg = (float)g_deg[row] + 1.0f;
            float inv = 1.0f / deg;
            bool  has = (g_cluster_edges[cl[row]] > 0);
            bool  src = (g_is_src[row] != 0);
            #pragma unroll
            for (int nt = 0; nt < 4; nt++) {
                int ncol = nwp * 32 + nt * 8 + tg * 2;
                float2 v = make_float2(acc[mt][nt][half * 2],
                                       acc[mt][nt][half * 2 + 1]);
                if (src) *(float2*)(g_xw + row * DD + ncol) = v;
                float2 o;
                if (has) {
                    o.x = fmaf(v.x, inv, bias[ncol]);
                    o.y = fmaf(v.y, inv, bias[ncol + 1]);
                } else {
                    o = *(const float2*)(X + row * DD + ncol);
                }
                *(float2*)(out + row * DD + ncol) = o;
            }
        }
    }
}

// ---------------- kernel 5: scatter over compacted intra edges --------------
__global__ void scatter_kernel(float* __restrict__ out) {
    int cnt  = g_intra_count;
    int gtid = blockIdx.x * blockDim.x + threadIdx.x;
    int warp = gtid >> 5;
    int lane = gtid & 31;
    int nw   = (gridDim.x * blockDim.x) >> 5;

    for (int e = warp; e < cnt; e += nw) {
        int s = g_intra_src[e];
        int d = g_intra_dst[e];
        float w = g_dinv[s] * g_dinv[d];
        float4 v = ((const float4*)(g_xw + s * DD))[lane];
        float* o = out + d * DD + lane * 4;
        atomicAdd(o + 0, w * v.x);
        atomicAdd(o + 1, w * v.y);
        atomicAdd(o + 2, w * v.z);
        atomicAdd(o + 3, w * v.w);
    }
}

// ---------------- launch ----------------
extern "C" void kernel_launch(void* const* d_in, const int* in_sizes, int n_in,
                              void* d_out, int out_size) {
    const float* X  = (const float*)d_in[0];
    const float* W  = (const float*)d_in[1];
    const float* b  = (const float*)d_in[2];
    // d_in[3] = edge_attr (unused)
    const int* cl = (const int*)d_in[4];
    const int* ei = (const int*)d_in[5];
    float* out = (float*)d_out;

    const int N = in_sizes[4];
    const int E = in_sizes[3];

    cudaFuncSetAttribute(gemm_fused_kernel,
                         cudaFuncAttributeMaxDynamicSharedMemorySize, SM_TOT);

    zero_kernel<<<(NN + 255) / 256, 256>>>();
    wprep_kernel<<<(DD * DD + 255) / 256, 256>>>(W);
    edge_pass_kernel<<<(E + 255) / 256, 256>>>(ei, cl, E);
    gemm_fused_kernel<<<(N + 63) / 64, 256, SM_TOT>>>(X, b, cl, out, N);
    scatter_kernel<<<512, 256>>>(out);
}